// round 17
// baseline (speedup 1.0000x reference)
#include <cuda_runtime.h>

#define DTV      0.02f
#define SQRT_DT  0.141421356237309515f
#define SIGMA    0.5f
#define NSTEP    50
#define BATCH    4096
#define PPC      32            // paths per CTA
#define NCTA     (BATCH / PPC) // 128
#define NTHR     384           // 8 Y-warps + 4 q-warps

typedef unsigned long long u64;

// ---- shared-memory layout (float offsets) ----
#define W_IN   0       // [2][64] = 128
#define B_IN   128     // 64
#define W_H    192     // [3][64][64] = 12288
#define B_H    12480   // [3][64] = 192
#define W_OUT  12672   // 64
#define B_OUT  12736   // 1 (+3 pad)
#define NET_SZ 12740
// activations: plain [64 rows][32 paths] floats, 128B rows
#define ABUF     2048
#define OFF_X0   (2 * NET_SZ)
#define OFF_DX0  (OFF_X0  + ABUF)
#define OFF_X1   (OFF_DX0 + ABUF)
#define OFF_DX1  (OFF_X1  + ABUF)
#define OFF_QX0  (OFF_DX1 + ABUF)
#define OFF_QX1  (OFF_QX0 + ABUF)
#define OFF_HD2  (OFF_QX1 + ABUF)     // DOUBLE buffer: 2 x 192
// Y K-half exchange: [8][128] u64 each half (h rows 0-3, d rows 4-7)
#define OFF_EXA  (OFF_HD2 + 384)      // 2048 floats
#define OFF_EXB  (OFF_EXA + 2048)
// q K-half exchange: [8][64] u64 each half
#define OFF_EQA  (OFF_EXB + 2048)     // 1024 floats
#define OFF_EQB  (OFF_EQA + 1024)
#define SMEM_FLOATS (OFF_EQB + 1024)
#define SMEM_BYTES  (SMEM_FLOATS * 4) // ~173 KB

#define BARY() asm volatile("bar.sync 1, 256;" ::: "memory")
#define BARQ() asm volatile("bar.sync 2, 128;" ::: "memory")

__device__ float g_part[NCTA];
__device__ int   g_count = 0;

__device__ __forceinline__ void cpf(float* d, const float* s, int n, int tid) {
    for (int i = tid; i < n; i += NTHR) d[i] = s[i];
}

__device__ __forceinline__ u64 fma2(u64 a, u64 b, u64 c) {
    u64 d;
    asm("fma.rn.f32x2 %0, %1, %2, %3;" : "=l"(d) : "l"(a), "l"(b), "l"(c));
    return d;
}
__device__ __forceinline__ u64 add2(u64 a, u64 b) {
    u64 d;
    asm("add.rn.f32x2 %0, %1, %2;" : "=l"(d) : "l"(a), "l"(b));
    return d;
}
__device__ __forceinline__ u64 pk(float lo, float hi) {
    u64 r;
    asm("mov.b64 %0, {%1, %2};" : "=l"(r) : "f"(lo), "f"(hi));
    return r;
}
__device__ __forceinline__ void upk(u64 v, float& lo, float& hi) {
    asm("mov.b64 {%0, %1}, %2;" : "=f"(lo), "=f"(hi) : "l"(v));
}

// ---- Y hidden layer: 4j x 4p tile, K-half split + exchange ----
// half 0: i in [0,32), keeps rows j0,j0+1 (gives j0+2,j0+3)
// half 1: i in [32,64), keeps rows j0+2,j0+3 (gives j0,j0+1)
__device__ __forceinline__ void layerY4(
    const float* __restrict__ Wy, const float* __restrict__ by,
    const float* __restrict__ X,  const float* __restrict__ DX,
    float* __restrict__ Xn, float* __restrict__ DXn,
    u64* __restrict__ EXA, u64* __restrict__ EXB,
    int half, int xid, int j0, int p0)
{
    const int ib = half * 32;
    u64 h[4][2], d[4][2];
#pragma unroll
    for (int jj = 0; jj < 4; jj++) {
        h[jj][0] = 0ull; h[jj][1] = 0ull;
        d[jj][0] = 0ull; d[jj][1] = 0ull;
    }

#pragma unroll 4
    for (int k = 0; k < 32; k++) {
        int i = ib + k;
        float4 w = *(const float4*)(Wy + i * 64 + j0);
        ulonglong2 xv = *(const ulonglong2*)(X  + i * 32 + p0);
        ulonglong2 dv = *(const ulonglong2*)(DX + i * 32 + p0);
        float wv[4] = {w.x, w.y, w.z, w.w};
#pragma unroll
        for (int jj = 0; jj < 4; jj++) {
            u64 w2 = pk(wv[jj], wv[jj]);
            h[jj][0] = fma2(w2, xv.x, h[jj][0]);
            h[jj][1] = fma2(w2, xv.y, h[jj][1]);
            d[jj][0] = fma2(w2, dv.x, d[jj][0]);
            d[jj][1] = fma2(w2, dv.y, d[jj][1]);
        }
    }

    // exchange: write the 2 rows this half gives away
    {
        u64* EXw = half ? EXB : EXA;
        int give = half ? 0 : 2;
#pragma unroll
        for (int t = 0; t < 2; t++)
#pragma unroll
            for (int pr = 0; pr < 2; pr++) {
                EXw[(t * 2 + pr) * 128 + xid]     = h[give + t][pr];
                EXw[(4 + t * 2 + pr) * 128 + xid] = d[give + t][pr];
            }
    }
    BARY();
    {
        const u64* EXr = half ? EXA : EXB;
        int keep = half ? 2 : 0;
#pragma unroll
        for (int t = 0; t < 2; t++) {
            u64 hh0 = add2(h[keep + t][0], EXr[(t * 2 + 0) * 128 + xid]);
            u64 hh1 = add2(h[keep + t][1], EXr[(t * 2 + 1) * 128 + xid]);
            u64 dd0 = add2(d[keep + t][0], EXr[(4 + t * 2 + 0) * 128 + xid]);
            u64 dd1 = add2(d[keep + t][1], EXr[(4 + t * 2 + 1) * 128 + xid]);
            int r = j0 + keep + t;
            float bv = by[r];
            float hv[4], dv_[4], s[4], c[4];
            upk(hh0, hv[0], hv[1]); upk(hh1, hv[2], hv[3]);
            upk(dd0, dv_[0], dv_[1]); upk(dd1, dv_[2], dv_[3]);
#pragma unroll
            for (int p = 0; p < 4; p++) __sincosf(hv[p] + bv, &s[p], &c[p]);
            *(float4*)(Xn  + r * 32 + p0) = make_float4(s[0], s[1], s[2], s[3]);
            *(float4*)(DXn + r * 32 + p0) =
                make_float4(c[0] * dv_[0], c[1] * dv_[1],
                            c[2] * dv_[2], c[3] * dv_[3]);
        }
    }
    BARY();
}

// ---- q hidden layer: 8j x 4p tile, K-half split + exchange (R16-proven) ----
__device__ __forceinline__ void layerQ8(
    const float* __restrict__ Wq, const float* __restrict__ bq,
    const float* __restrict__ QX, float* __restrict__ QXn,
    u64* __restrict__ EQA, u64* __restrict__ EQB,
    int half, int xid, int j0, int p0)
{
    const int ib = half * 32;
    u64 a[8][2];
#pragma unroll
    for (int jj = 0; jj < 8; jj++) { a[jj][0] = 0ull; a[jj][1] = 0ull; }

#pragma unroll 4
    for (int k = 0; k < 32; k++) {
        int i = ib + k;
        float4 wA = *(const float4*)(Wq + i * 64 + j0);
        float4 wB = *(const float4*)(Wq + i * 64 + j0 + 4);
        ulonglong2 qv = *(const ulonglong2*)(QX + i * 32 + p0);
        float wv[8] = {wA.x, wA.y, wA.z, wA.w, wB.x, wB.y, wB.z, wB.w};
#pragma unroll
        for (int jj = 0; jj < 8; jj++) {
            u64 w2 = pk(wv[jj], wv[jj]);
            a[jj][0] = fma2(w2, qv.x, a[jj][0]);
            a[jj][1] = fma2(w2, qv.y, a[jj][1]);
        }
    }

    {
        u64* EQw = half ? EQB : EQA;
        int give = half ? 0 : 4;
#pragma unroll
        for (int t = 0; t < 4; t++)
#pragma unroll
            for (int pr = 0; pr < 2; pr++)
                EQw[(t * 2 + pr) * 64 + xid] = a[give + t][pr];
    }
    BARQ();
    {
        const u64* EQr = half ? EQA : EQB;
        int keep = half ? 4 : 0;
#pragma unroll
        for (int t = 0; t < 4; t++) {
            u64 a0 = add2(a[keep + t][0], EQr[(t * 2 + 0) * 64 + xid]);
            u64 a1 = add2(a[keep + t][1], EQr[(t * 2 + 1) * 64 + xid]);
            int r = j0 + keep + t;
            float bv = bq[r];
            float v[4];
            upk(a0, v[0], v[1]); upk(a1, v[2], v[3]);
#pragma unroll
            for (int p = 0; p < 4; p++) v[p] = __sinf(v[p] + bv);
            *(float4*)(QXn + r * 32 + p0) = make_float4(v[0], v[1], v[2], v[3]);
        }
    }
    BARQ();
}

// Full fused eval on register y state; heads write hdw; ends CTA-synced.
__device__ __forceinline__ void eval_all(float* sm, float tval, float* hdw,
                                         const float yreg[4],
                                         int tid, int wid, int lane)
{
    const float* netY = sm;
    const float* netQ = sm + NET_SZ;
    float* X0  = sm + OFF_X0;
    float* DX0 = sm + OFF_DX0;
    float* X1  = sm + OFF_X1;
    float* DX1 = sm + OFF_DX1;
    float* QX0 = sm + OFF_QX0;
    float* QX1 = sm + OFF_QX1;
    u64* EXA = (u64*)(sm + OFF_EXA);
    u64* EXB = (u64*)(sm + OFF_EXB);
    u64* EQA = (u64*)(sm + OFF_EQA);
    u64* EQB = (u64*)(sm + OFF_EQB);

    if (tid < 256) {
        // ================= team Y (8 warps) =================
        const int ch = tid & 7, p0c = ch * 4;
#pragma unroll
        for (int k = 0; k < 2; k++) {
            int r = (tid >> 3) + k * 32;
            float wt = netY[W_IN + r], wy = netY[W_IN + 64 + r];
            float tb = fmaf(tval, wt, netY[B_IN + r]);
            float s[4], c[4];
#pragma unroll
            for (int p = 0; p < 4; p++)
                __sincosf(fmaf(yreg[p], wy, tb), &s[p], &c[p]);
            *(float4*)(X0 + r * 32 + p0c) = make_float4(s[0], s[1], s[2], s[3]);
            *(float4*)(DX0 + r * 32 + p0c) =
                make_float4(c[0] * wy, c[1] * wy, c[2] * wy, c[3] * wy);
        }
        BARY();

        const int half = tid >> 7;        // K-half
        const int xid  = tid & 127;
        const int j0 = (xid & 15) * 4;    // 16 j-groups of 4
        const int p0 = (xid >> 4) * 4;    // 8 path-quads
        layerY4(netY + W_H,        netY + B_H,       X0, DX0, X1, DX1,
                EXA, EXB, half, xid, j0, p0);
        layerY4(netY + W_H + 4096, netY + B_H + 64,  X1, DX1, X0, DX0,
                EXA, EXB, half, xid, j0, p0);
        layerY4(netY + W_H + 8192, netY + B_H + 128, X0, DX0, X1, DX1,
                EXA, EXB, half, xid, j0, p0);

        // heads: warps 0-3 = (head Y/dY) x (i-half)
        if (wid < 4) {
            int head = wid >> 1, ih = wid & 1;
            const float* src = head ? DX1 : X1;
            const float* wv  = netY + W_OUT;
            int i0 = ih * 32;
            float a0 = 0.0f, a1 = 0.0f;
#pragma unroll 8
            for (int i = 0; i < 32; i += 2) {
                a0 = fmaf(src[(i0 + i) * 32 + lane],     wv[i0 + i],     a0);
                a1 = fmaf(src[(i0 + i + 1) * 32 + lane], wv[i0 + i + 1], a1);
            }
            hdw[head * 64 + ih * 32 + lane] = a0 + a1;
        }
    } else {
        // ================= team Q (4 warps) =================
        const int qt = tid - 256;
        const int ch = qt & 7, p0c = ch * 4;
#pragma unroll
        for (int k = 0; k < 4; k++) {
            int r = (qt >> 3) + k * 16;
            float wt = netQ[W_IN + r], wy = netQ[W_IN + 64 + r];
            float tb = fmaf(tval, wt, netQ[B_IN + r]);
            float sq[4];
#pragma unroll
            for (int p = 0; p < 4; p++)
                sq[p] = __sinf(fmaf(yreg[p], wy, tb));
            *(float4*)(QX0 + r * 32 + p0c) = make_float4(sq[0], sq[1], sq[2], sq[3]);
        }
        BARQ();

        const int half = qt >> 6;
        const int xid  = qt & 63;
        const int j0 = (xid >> 3) * 8;
        const int p0 = (xid & 7) * 4;
        layerQ8(netQ + W_H,        netQ + B_H,       QX0, QX1,
                EQA, EQB, half, xid, j0, p0);
        layerQ8(netQ + W_H + 4096, netQ + B_H + 64,  QX1, QX0,
                EQA, EQB, half, xid, j0, p0);
        layerQ8(netQ + W_H + 8192, netQ + B_H + 128, QX0, QX1,
                EQA, EQB, half, xid, j0, p0);

        // q head: warps 8,9 = i-halves
        if (wid < 10) {
            int ih = wid & 1;
            const float* wv = netQ + W_OUT;
            int i0 = ih * 32;
            float a0 = 0.0f, a1 = 0.0f;
#pragma unroll 8
            for (int i = 0; i < 32; i += 2) {
                a0 = fmaf(QX1[(i0 + i) * 32 + lane],     wv[i0 + i],     a0);
                a1 = fmaf(QX1[(i0 + i + 1) * 32 + lane], wv[i0 + i + 1], a1);
            }
            hdw[128 + ih * 32 + lane] = a0 + a1;
        }
    }
    __syncthreads();
}

__global__ __launch_bounds__(NTHR, 1) void fbsnn_main(
    const float* __restrict__ yWin,  const float* __restrict__ yBin,
    const float* __restrict__ yWh,   const float* __restrict__ yBh,
    const float* __restrict__ yWout, const float* __restrict__ yBout,
    const float* __restrict__ qWin,  const float* __restrict__ qBin,
    const float* __restrict__ qWh,   const float* __restrict__ qBh,
    const float* __restrict__ qWout, const float* __restrict__ qBout,
    const float* __restrict__ y0,    const float* __restrict__ dW,
    float* __restrict__ out)
{
    extern __shared__ float sm[];
    const int tid  = threadIdx.x;
    const int wid  = tid >> 5;
    const int lane = tid & 31;

    // ---- stage all weights into smem once ----
    cpf(sm + W_IN,  yWin, 128,   tid);
    cpf(sm + B_IN,  yBin, 64,    tid);
    cpf(sm + W_H,   yWh,  12288, tid);
    cpf(sm + B_H,   yBh,  192,   tid);
    cpf(sm + W_OUT, yWout, 64,   tid);
    if (tid == 0) sm[B_OUT] = yBout[0];
    float* smq = sm + NET_SZ;
    cpf(smq + W_IN,  qWin, 128,   tid);
    cpf(smq + B_IN,  qBin, 64,    tid);
    cpf(smq + W_H,   qWh,  12288, tid);
    cpf(smq + B_H,   qBh,  192,   tid);
    cpf(smq + W_OUT, qWout, 64,   tid);
    if (tid == 0) smq[B_OUT] = qBout[0];
    __syncthreads();

    const int pbase = blockIdx.x * PPC;
    const float ybias = sm[B_OUT];
    const float qbias = smq[B_OUT];

    // per-thread path chunk (4 paths) and register state
    const int ch = (tid < 256 ? tid : tid - 256) & 7;
    const float y0v = y0[0];
    float yreg[4] = {y0v, y0v, y0v, y0v};
    float dwc[4];
#pragma unroll
    for (int j = 0; j < 4; j++) dwc[j] = dW[pbase + ch * 4 + j];

    float ylane = y0v, dwlane = 0.0f;
    float lossAcc = 0.0f, Ytilde = 0.0f;
    if (wid == 0) dwlane = dW[pbase + lane];

    // initial eval at t = 0 -> HD buf0
    eval_all(sm, 0.0f, sm + OFF_HD2, yreg, tid, wid, lane);

    for (int n = 0; n < NSTEP; n++) {
        const float* hdr = sm + OFF_HD2 + (n & 1) * 192;
        float* hdw = sm + OFF_HD2 + ((n + 1) & 1) * 192;

        // per-thread y update from q-head partials (bitwise-identical dup)
#pragma unroll
        for (int j = 0; j < 4; j++) {
            int p = ch * 4 + j;
            float qv = hdr[128 + p] + hdr[160 + p] + qbias;
            yreg[j] += qv * DTV + SIGMA * (SQRT_DT * dwc[j]);
        }
        if (n + 1 < NSTEP) {
#pragma unroll
            for (int j = 0; j < 4; j++)
                dwc[j] = dW[(n + 1) * BATCH + pbase + ch * 4 + j];
        }

        if (wid == 0) {
            float Yv  = hdr[lane]       + hdr[32 + lane] + ybias;
            float dYv = hdr[64 + lane]  + hdr[96 + lane];
            float ql  = hdr[128 + lane] + hdr[160 + lane] + qbias;
            if (n > 0) {
                float e = Yv - Ytilde;
                lossAcc = fmaf(e, e, lossAcc);
            }
            float dwn = SQRT_DT * dwlane;
            Ytilde = Yv - ql * ql * DTV + SIGMA * dYv * dwn;
            ylane += ql * DTV + SIGMA * dwn;
            if (n + 1 < NSTEP) dwlane = dW[(n + 1) * BATCH + pbase + lane];
        }

        eval_all(sm, (float)(n + 1) * DTV, hdw, yreg, tid, wid, lane);
    }

    if (wid == 0) {
        const float* hdf = sm + OFF_HD2 + (NSTEP & 1) * 192;
        float Yv  = hdf[lane]      + hdf[32 + lane] + ybias;
        float dYv = hdf[64 + lane] + hdf[96 + lane];
        float e = Yv - Ytilde;
        lossAcc = fmaf(e, e, lossAcc);
        float yN = ylane;
        float e1 = Yv - yN * yN;
        float e2 = dYv - 2.0f * yN;
        lossAcc = fmaf(e1, e1, fmaf(e2, e2, lossAcc));
#pragma unroll
        for (int o = 16; o > 0; o >>= 1)
            lossAcc += __shfl_down_sync(0xffffffffu, lossAcc, o);
        if (lane == 0) g_part[blockIdx.x] = lossAcc;
    }

    // ---- last-CTA deterministic reduction (single launch) ----
    if (tid == 0) {
        __threadfence();
        int old = atomicAdd(&g_count, 1);
        if (old == NCTA - 1) {
            __threadfence();
            float acc = 0.0f;
#pragma unroll 8
            for (int i = 0; i < NCTA; i++) acc += g_part[i];
            out[0] = acc * (1.0f / (float)BATCH);
            g_count = 0;
        }
    }
}

extern "C" void kernel_launch(void* const* d_in, const int* in_sizes, int n_in,
                              void* d_out, int out_size)
{
    const float *yWin, *yBin, *yWh, *yBh, *yWout, *yBout;
    const float *qWin, *qBin, *qWh, *qBh, *qWout, *qBout;
    const float *y0, *dW;

    if (in_sizes[0] == 1) {
        y0    = (const float*)d_in[0];
        yWin  = (const float*)d_in[1];
        yBin  = (const float*)d_in[2];
        yWh   = (const float*)d_in[3];
        yBh   = (const float*)d_in[4];
        yWout = (const float*)d_in[5];
        yBout = (const float*)d_in[6];
        qWin  = (const float*)d_in[7];
        qBin  = (const float*)d_in[8];
        qWh   = (const float*)d_in[9];
        qBh   = (const float*)d_in[10];
        qWout = (const float*)d_in[11];
        qBout = (const float*)d_in[12];
        dW    = (const float*)d_in[13];
    } else {
        yWin  = (const float*)d_in[0];
        yBin  = (const float*)d_in[1];
        yWh   = (const float*)d_in[2];
        yBh   = (const float*)d_in[3];
        yWout = (const float*)d_in[4];
        yBout = (const float*)d_in[5];
        qWin  = (const float*)d_in[6];
        qBin  = (const float*)d_in[7];
        qWh   = (const float*)d_in[8];
        qBh   = (const float*)d_in[9];
        qWout = (const float*)d_in[10];
        qBout = (const float*)d_in[11];
        y0    = (const float*)d_in[12];
        dW    = (const float*)d_in[13];
    }

    cudaFuncSetAttribute(fbsnn_main, cudaFuncAttributeMaxDynamicSharedMemorySize,
                         SMEM_BYTES);

    fbsnn_main<<<NCTA, NTHR, SMEM_BYTES>>>(yWin, yBin, yWh, yBh, yWout, yBout,
                                           qWin, qBin, qWh, qBh, qWout, qBout,
                                           y0, dW, (float*)d_out);
}